// round 2
// baseline (speedup 1.0000x reference)
#include <cuda_runtime.h>
#include <math.h>

#define N_TOK 4096
#define DD 1024
#define EE 8
#define HH 2048
#define CAP 4096
#define BM 64
#define BN 64
#define BK 16

// Scratch (static __device__ — no runtime allocation).
__device__ int   g_cnt[EE];
__device__ int   g_off[EE];
__device__ int   g_tok[EE * CAP];
__device__ float g_gate[EE * CAP];
// 8192 expert-token rows + BM pad rows of H floats (~67.6 MB)
__device__ float g_h[(size_t)(2 * N_TOK + BM) * HH];

__global__ void k_init() {
    if (threadIdx.x < EE) g_cnt[threadIdx.x] = 0;
}

__global__ void k_zero_out(float* __restrict__ out, int n4) {
    int i = blockIdx.x * blockDim.x + threadIdx.x;
    if (i < n4) ((float4*)out)[i] = make_float4(0.f, 0.f, 0.f, 0.f);
}

// One warp per token: 8 logits, top-2, softmax over the two, scatter to lists.
__global__ void k_router(const float* __restrict__ x,
                         const float* __restrict__ Wr,
                         const float* __restrict__ br) {
    int gwarp = (blockIdx.x * blockDim.x + threadIdx.x) >> 5;
    int lane  = threadIdx.x & 31;
    if (gwarp >= N_TOK) return;
    const float* xr = x + (size_t)gwarp * DD;
    float acc[EE];
#pragma unroll
    for (int e = 0; e < EE; e++) acc[e] = 0.f;
    for (int d = lane; d < DD; d += 32) {
        float xv = xr[d];
        const float* w = Wr + d * EE;
#pragma unroll
        for (int e = 0; e < EE; e++) acc[e] += xv * w[e];
    }
#pragma unroll
    for (int e = 0; e < EE; e++) {
#pragma unroll
        for (int o = 16; o > 0; o >>= 1)
            acc[e] += __shfl_down_sync(0xffffffffu, acc[e], o);
    }
    if (lane == 0) {
        float lg[EE];
#pragma unroll
        for (int e = 0; e < EE; e++) lg[e] = acc[e] + br[e];
        int i1 = 0;
#pragma unroll
        for (int e = 1; e < EE; e++) if (lg[e] > lg[i1]) i1 = e;
        int i2 = (i1 == 0) ? 1 : 0;
#pragma unroll
        for (int e = 0; e < EE; e++)
            if (e != i1 && lg[e] > lg[i2]) i2 = e;
        // softmax over the two kept logits (others are exactly 0 weight)
        float e2 = expf(lg[i2] - lg[i1]);
        float s  = 1.0f + e2;
        float ga = 1.0f / s;
        float gb = e2 / s;
        int s1 = atomicAdd(&g_cnt[i1], 1);
        g_tok[i1 * CAP + s1]  = gwarp;
        g_gate[i1 * CAP + s1] = ga;
        int s2 = atomicAdd(&g_cnt[i2], 1);
        g_tok[i2 * CAP + s2]  = gwarp;
        g_gate[i2 * CAP + s2] = gb;
    }
}

__global__ void k_offsets() {
    int o = 0;
    for (int e = 0; e < EE; e++) { g_off[e] = o; o += g_cnt[e]; }
}

// GEMM1: g_h[row, n] = relu( x[tok, :] @ W1_e[:, n] + b1_e[n] )
__global__ __launch_bounds__(256) void k_gemm1(const float* __restrict__ x,
                                               const float* __restrict__ W1,
                                               const float* __restrict__ b1) {
    int e   = blockIdx.z;
    int cnt = g_cnt[e];
    int m0  = blockIdx.y * BM;
    if (m0 >= cnt) return;
    int n0  = blockIdx.x * BN;
    int off = g_off[e];

    __shared__ float As[BK][BM + 4];
    __shared__ float Bs[BK][BN + 4];

    int tid = threadIdx.x;
    int lm  = tid >> 4;          // 0..15 -> rows lm*4..lm*4+3
    int ln  = tid & 15;          // 0..15 -> cols ln*4..ln*4+3

    int a_m  = tid >> 2;         // 0..63
    int a_k4 = (tid & 3) << 2;   // 0,4,8,12
    bool am_ok = (m0 + a_m) < cnt;
    const float* Aptr = x;       // dummy; only deref when am_ok
    if (am_ok) {
        int tok = g_tok[e * CAP + m0 + a_m];
        Aptr = x + (size_t)tok * DD + a_k4;
    }
    int b_k  = tid >> 4;         // 0..15
    int b_n4 = (tid & 15) << 2;  // 0..60
    const float* Bptr = W1 + (size_t)e * DD * HH + (size_t)b_k * HH + n0 + b_n4;

    float c[4][4];
#pragma unroll
    for (int i = 0; i < 4; i++)
#pragma unroll
        for (int j = 0; j < 4; j++) c[i][j] = 0.f;

    for (int k0 = 0; k0 < DD; k0 += BK) {
        float4 av = am_ok ? *(const float4*)(Aptr + k0)
                          : make_float4(0.f, 0.f, 0.f, 0.f);
        As[a_k4 + 0][a_m] = av.x;
        As[a_k4 + 1][a_m] = av.y;
        As[a_k4 + 2][a_m] = av.z;
        As[a_k4 + 3][a_m] = av.w;
        *(float4*)&Bs[b_k][b_n4] = *(const float4*)(Bptr + (size_t)k0 * HH);
        __syncthreads();
#pragma unroll
        for (int k = 0; k < BK; k++) {
            float4 a = *(const float4*)&As[k][lm << 2];
            float4 b = *(const float4*)&Bs[k][ln << 2];
            c[0][0] += a.x * b.x; c[0][1] += a.x * b.y; c[0][2] += a.x * b.z; c[0][3] += a.x * b.w;
            c[1][0] += a.y * b.x; c[1][1] += a.y * b.y; c[1][2] += a.y * b.z; c[1][3] += a.y * b.w;
            c[2][0] += a.z * b.x; c[2][1] += a.z * b.y; c[2][2] += a.z * b.z; c[2][3] += a.z * b.w;
            c[3][0] += a.w * b.x; c[3][1] += a.w * b.y; c[3][2] += a.w * b.z; c[3][3] += a.w * b.w;
        }
        __syncthreads();
    }

    float4 bias = *(const float4*)(b1 + (size_t)e * HH + n0 + (ln << 2));
#pragma unroll
    for (int i = 0; i < 4; i++) {
        int m = m0 + (lm << 2) + i;
        if (m < cnt) {
            float4 v;
            v.x = fmaxf(c[i][0] + bias.x, 0.f);
            v.y = fmaxf(c[i][1] + bias.y, 0.f);
            v.z = fmaxf(c[i][2] + bias.z, 0.f);
            v.w = fmaxf(c[i][3] + bias.w, 0.f);
            *(float4*)(g_h + (size_t)(off + m) * HH + n0 + (ln << 2)) = v;
        }
    }
}

// GEMM2: out[tok, n] += gate * ( g_h[row, :] @ W2_e[:, n] + b2_e[n] )
__global__ __launch_bounds__(256) void k_gemm2(const float* __restrict__ W2,
                                               const float* __restrict__ b2,
                                               float* __restrict__ out) {
    int e   = blockIdx.z;
    int cnt = g_cnt[e];
    int m0  = blockIdx.y * BM;
    if (m0 >= cnt) return;
    int n0  = blockIdx.x * BN;
    int off = g_off[e];

    __shared__ float As[BK][BM + 4];
    __shared__ float Bs[BK][BN + 4];

    int tid = threadIdx.x;
    int lm  = tid >> 4;
    int ln  = tid & 15;

    int a_m  = tid >> 2;
    int a_k4 = (tid & 3) << 2;
    bool am_ok = (m0 + a_m) < cnt;
    const float* Aptr = g_h + (size_t)(off + m0 + a_m) * HH + a_k4;
    int b_k  = tid >> 4;
    int b_n4 = (tid & 15) << 2;
    const float* Bptr = W2 + (size_t)e * HH * DD + (size_t)b_k * DD + n0 + b_n4;

    float c[4][4];
#pragma unroll
    for (int i = 0; i < 4; i++)
#pragma unroll
        for (int j = 0; j < 4; j++) c[i][j] = 0.f;

    for (int k0 = 0; k0 < HH; k0 += BK) {
        float4 av = am_ok ? *(const float4*)(Aptr + k0)
                          : make_float4(0.f, 0.f, 0.f, 0.f);
        As[a_k4 + 0][a_m] = av.x;
        As[a_k4 + 1][a_m] = av.y;
        As[a_k4 + 2][a_m] = av.z;
        As[a_k4 + 3][a_m] = av.w;
        *(float4*)&Bs[b_k][b_n4] = *(const float4*)(Bptr + (size_t)k0 * DD);
        __syncthreads();
#pragma unroll
        for (int k = 0; k < BK; k++) {
            float4 a = *(const float4*)&As[k][lm << 2];
            float4 b = *(const float4*)&Bs[k][ln << 2];
            c[0][0] += a.x * b.x; c[0][1] += a.x * b.y; c[0][2] += a.x * b.z; c[0][3] += a.x * b.w;
            c[1][0] += a.y * b.x; c[1][1] += a.y * b.y; c[1][2] += a.y * b.z; c[1][3] += a.y * b.w;
            c[2][0] += a.z * b.x; c[2][1] += a.z * b.y; c[2][2] += a.z * b.z; c[2][3] += a.z * b.w;
            c[3][0] += a.w * b.x; c[3][1] += a.w * b.y; c[3][2] += a.w * b.z; c[3][3] += a.w * b.w;
        }
        __syncthreads();
    }

    const float* b2e = b2 + (size_t)e * DD + n0 + (ln << 2);
    float4 bias = *(const float4*)b2e;
#pragma unroll
    for (int i = 0; i < 4; i++) {
        int m = m0 + (lm << 2) + i;
        if (m < cnt) {
            int   tok  = g_tok[e * CAP + m];
            float gate = g_gate[e * CAP + m];
            float* orow = out + (size_t)tok * DD + n0 + (ln << 2);
            atomicAdd(orow + 0, gate * (c[i][0] + bias.x));
            atomicAdd(orow + 1, gate * (c[i][1] + bias.y));
            atomicAdd(orow + 2, gate * (c[i][2] + bias.z));
            atomicAdd(orow + 3, gate * (c[i][3] + bias.w));
        }
    }
}

extern "C" void kernel_launch(void* const* d_in, const int* in_sizes, int n_in,
                              void* d_out, int out_size) {
    const float* x  = (const float*)d_in[0];
    const float* Wr = (const float*)d_in[1];
    const float* br = (const float*)d_in[2];
    const float* W1 = (const float*)d_in[3];
    const float* b1 = (const float*)d_in[4];
    const float* W2 = (const float*)d_in[5];
    const float* b2 = (const float*)d_in[6];
    float* out = (float*)d_out;

    int n4 = out_size / 4;  // out_size = 4096*1024, divisible by 4
    k_zero_out<<<(n4 + 255) / 256, 256>>>(out, n4);
    k_init<<<1, 32>>>();
    k_router<<<(N_TOK * 32 + 255) / 256, 256>>>(x, Wr, br);
    k_offsets<<<1, 1>>>();
    k_gemm1<<<dim3(HH / BN, N_TOK / BM, EE), 256>>>(x, W1, b1);
    k_gemm2<<<dim3(DD / BN, N_TOK / BM, EE), 256>>>(W2, b2, out);
}

// round 4
// speedup vs baseline: 2.0700x; 2.0700x over previous
#include <cuda_runtime.h>
#include <cuda_bf16.h>
#include <cstdint>
#include <math.h>

#define N_TOK 4096
#define DD 1024
#define EE 8
#define HH 2048
#define CAP 4096

#define TM 128
#define TN 128
#define KC 32            // bf16 k-elements per smem chunk
#define ASTRIDE 80       // smem row stride bytes (32 bf16 = 64B + 16B pad)
#define MATB (128 * ASTRIDE)          // 10240 B per matrix
#define STAGEB (4 * MATB)             // Ahi Alo Bhi Blo
#define SMEM_BYTES (2 * STAGEB)       // 81920

// ---------------- scratch (static __device__; no runtime allocation) --------
__device__ int   g_cnt[EE];
__device__ int   g_off[EE];
__device__ int   g_tok[EE * CAP];
__device__ float g_gate[EE * CAP];
__device__ __align__(256) __nv_bfloat16 g_x_hi[(size_t)N_TOK * DD];
__device__ __align__(256) __nv_bfloat16 g_x_lo[(size_t)N_TOK * DD];
__device__ __align__(256) __nv_bfloat16 g_w1_hi[(size_t)EE * HH * DD];  // [e][n=H][k=D]
__device__ __align__(256) __nv_bfloat16 g_w1_lo[(size_t)EE * HH * DD];
__device__ __align__(256) __nv_bfloat16 g_w2_hi[(size_t)EE * DD * HH];  // [e][n=D][k=H]
__device__ __align__(256) __nv_bfloat16 g_w2_lo[(size_t)EE * DD * HH];
__device__ __align__(256) __nv_bfloat16 g_h_hi[(size_t)(2 * N_TOK + TM) * HH];
__device__ __align__(256) __nv_bfloat16 g_h_lo[(size_t)(2 * N_TOK + TM) * HH];

// ---------------- PTX helpers -----------------------------------------------
__device__ __forceinline__ uint32_t smem_u32(const void* p) {
    uint32_t a;
    asm("{ .reg .u64 t; cvta.to.shared.u64 t, %1; cvt.u32.u64 %0, t; }"
        : "=r"(a) : "l"(p));
    return a;
}

__device__ __forceinline__ void cp16(uint32_t dst, const void* src, int sz) {
    asm volatile("cp.async.cg.shared.global [%0], [%1], 16, %2;"
                 :: "r"(dst), "l"(src), "r"(sz));
}
#define CP_COMMIT() asm volatile("cp.async.commit_group;" ::: "memory")
#define CP_WAIT1()  asm volatile("cp.async.wait_group 1;" ::: "memory")
#define CP_WAIT0()  asm volatile("cp.async.wait_group 0;" ::: "memory")

#define LDSM4(R, a) \
    asm volatile("ldmatrix.sync.aligned.m8n8.x4.shared.b16 {%0,%1,%2,%3}, [%4];" \
                 : "=r"((R)[0]), "=r"((R)[1]), "=r"((R)[2]), "=r"((R)[3]) : "r"(a))

#define MMA(C, A, B0, B1) \
    asm volatile("mma.sync.aligned.m16n8k16.row.col.f32.bf16.bf16.f32 " \
                 "{%0,%1,%2,%3}, {%4,%5,%6,%7}, {%8,%9}, {%0,%1,%2,%3};" \
                 : "+f"((C)[0]), "+f"((C)[1]), "+f"((C)[2]), "+f"((C)[3]) \
                 : "r"((A)[0]), "r"((A)[1]), "r"((A)[2]), "r"((A)[3]), \
                   "r"(B0), "r"(B1))

// ---------------- small kernels ----------------------------------------------
__global__ void k_init() {
    if (threadIdx.x < EE) g_cnt[threadIdx.x] = 0;
}

__global__ void k_zero_out(float* __restrict__ out, int n4) {
    int i = blockIdx.x * blockDim.x + threadIdx.x;
    if (i < n4) ((float4*)out)[i] = make_float4(0.f, 0.f, 0.f, 0.f);
}

__global__ void k_conv_x(const float* __restrict__ x) {
    int i = blockIdx.x * blockDim.x + threadIdx.x;
    if (i >= N_TOK * DD / 4) return;
    float4 v = ((const float4*)x)[i];
    __nv_bfloat162 h0, h1, l0, l1;
    h0.x = __float2bfloat16(v.x); h0.y = __float2bfloat16(v.y);
    h1.x = __float2bfloat16(v.z); h1.y = __float2bfloat16(v.w);
    l0.x = __float2bfloat16(v.x - __bfloat162float(h0.x));
    l0.y = __float2bfloat16(v.y - __bfloat162float(h0.y));
    l1.x = __float2bfloat16(v.z - __bfloat162float(h1.x));
    l1.y = __float2bfloat16(v.w - __bfloat162float(h1.y));
    ((__nv_bfloat162*)g_x_hi)[2 * i]     = h0;
    ((__nv_bfloat162*)g_x_hi)[2 * i + 1] = h1;
    ((__nv_bfloat162*)g_x_lo)[2 * i]     = l0;
    ((__nv_bfloat162*)g_x_lo)[2 * i + 1] = l1;
}

// Transpose + split: W[e][K][N] -> dst[e][N][K] (hi/lo).  which: 1=W1, 2=W2
__global__ void k_conv_w(const float* __restrict__ W, int which, int K, int N) {
    __shared__ float t[32][33];
    int e  = blockIdx.z;
    int n0 = blockIdx.x * 32;
    int k0 = blockIdx.y * 32;
    const float* We = W + (size_t)e * K * N;
    for (int r = threadIdx.y; r < 32; r += 8)
        t[r][threadIdx.x] = We[(size_t)(k0 + r) * N + n0 + threadIdx.x];
    __syncthreads();
    __nv_bfloat16* dhi = (which == 1) ? g_w1_hi : g_w2_hi;
    __nv_bfloat16* dlo = (which == 1) ? g_w1_lo : g_w2_lo;
    size_t base = (size_t)e * K * N;
    for (int r = threadIdx.y; r < 32; r += 8) {
        float v = t[threadIdx.x][r];  // = W[e][k0+tx][n0+r]
        __nv_bfloat16 hi = __float2bfloat16(v);
        __nv_bfloat16 lo = __float2bfloat16(v - __bfloat162float(hi));
        size_t o = base + (size_t)(n0 + r) * K + k0 + threadIdx.x;
        dhi[o] = hi;
        dlo[o] = lo;
    }
}

__global__ void k_router(const float* __restrict__ x,
                         const float* __restrict__ Wr,
                         const float* __restrict__ br) {
    int gwarp = (blockIdx.x * blockDim.x + threadIdx.x) >> 5;
    int lane  = threadIdx.x & 31;
    if (gwarp >= N_TOK) return;
    const float* xr = x + (size_t)gwarp * DD;
    float acc[EE];
#pragma unroll
    for (int e = 0; e < EE; e++) acc[e] = 0.f;
    for (int d = lane; d < DD; d += 32) {
        float xv = xr[d];
        const float* w = Wr + d * EE;
#pragma unroll
        for (int e = 0; e < EE; e++) acc[e] += xv * w[e];
    }
#pragma unroll
    for (int e = 0; e < EE; e++) {
#pragma unroll
        for (int o = 16; o > 0; o >>= 1)
            acc[e] += __shfl_down_sync(0xffffffffu, acc[e], o);
    }
    if (lane == 0) {
        float lg[EE];
#pragma unroll
        for (int e = 0; e < EE; e++) lg[e] = acc[e] + br[e];
        int i1 = 0;
#pragma unroll
        for (int e = 1; e < EE; e++) if (lg[e] > lg[i1]) i1 = e;
        int i2 = (i1 == 0) ? 1 : 0;
#pragma unroll
        for (int e = 0; e < EE; e++)
            if (e != i1 && lg[e] > lg[i2]) i2 = e;
        float e2 = expf(lg[i2] - lg[i1]);
        float s  = 1.0f + e2;
        int s1 = atomicAdd(&g_cnt[i1], 1);
        g_tok[i1 * CAP + s1]  = gwarp;
        g_gate[i1 * CAP + s1] = 1.0f / s;
        int s2 = atomicAdd(&g_cnt[i2], 1);
        g_tok[i2 * CAP + s2]  = gwarp;
        g_gate[i2 * CAP + s2] = e2 / s;
    }
}

__global__ void k_offsets() {
    int o = 0;
    for (int e = 0; e < EE; e++) { g_off[e] = o; o += g_cnt[e]; }
}

// ---------------- HMMA compute core ------------------------------------------
// Warp tile 32(m) x 64(n). 3-product split-bf16, fp32 accumulate.
__device__ __forceinline__ void compute_chunk(
    uint32_t sA_hi, uint32_t sA_lo, uint32_t sB_hi, uint32_t sB_lo,
    int mw, int nw, int lane, float c[2][8][4]) {
#pragma unroll
    for (int ks = 0; ks < 2; ks++) {
        int kb = ks * 32 + (lane >> 4) * 16;   // byte offset within row
        uint32_t ahi[2][4], alo[2][4], bhi[4][4], blo[4][4];
#pragma unroll
        for (int mf = 0; mf < 2; mf++) {
            uint32_t off = (uint32_t)(mw * 32 + mf * 16 + (lane & 15)) * ASTRIDE + kb;
            LDSM4(ahi[mf], sA_hi + off);
            LDSM4(alo[mf], sA_lo + off);
        }
#pragma unroll
        for (int ng = 0; ng < 4; ng++) {
            uint32_t off = (uint32_t)(nw * 64 + ng * 16 + (lane & 15)) * ASTRIDE + kb;
            LDSM4(bhi[ng], sB_hi + off);
            LDSM4(blo[ng], sB_lo + off);
        }
#pragma unroll
        for (int mf = 0; mf < 2; mf++) {
#pragma unroll
            for (int ng = 0; ng < 4; ng++) {
                MMA(c[mf][2 * ng],     ahi[mf], bhi[ng][0], bhi[ng][2]);
                MMA(c[mf][2 * ng + 1], ahi[mf], bhi[ng][1], bhi[ng][3]);
                MMA(c[mf][2 * ng],     ahi[mf], blo[ng][0], blo[ng][2]);
                MMA(c[mf][2 * ng + 1], ahi[mf], blo[ng][1], blo[ng][3]);
                MMA(c[mf][2 * ng],     alo[mf], bhi[ng][0], bhi[ng][2]);
                MMA(c[mf][2 * ng + 1], alo[mf], bhi[ng][1], bhi[ng][3]);
            }
        }
    }
}

// issue one chunk's cp.async loads (per thread: 8 x 16B)
__device__ __forceinline__ void load_chunk(
    uint32_t stage, const char* ahi, const char* alo,
    const char* bhi, const char* blo, bool rok, int tid, int kbyte) {
    int row = tid >> 1;
    int j0  = (tid & 1) * 2;
    int asz = rok ? 16 : 0;
#pragma unroll
    for (int j = j0; j < j0 + 2; j++) {
        uint32_t so = (uint32_t)row * ASTRIDE + j * 16;
        int go = kbyte + j * 16;
        cp16(stage + 0 * MATB + so, ahi + go, asz);
        cp16(stage + 1 * MATB + so, alo + go, asz);
        cp16(stage + 2 * MATB + so, bhi + go, 16);
        cp16(stage + 3 * MATB + so, blo + go, 16);
    }
}

// GEMM1: h = relu(Xg @ W1^T + b1) -> split g_h_hi/lo
__global__ void __launch_bounds__(256) k_mm1(const float* __restrict__ b1) {
    extern __shared__ char smem[];
    int e   = blockIdx.z;
    int cnt = g_cnt[e];
    int m0  = blockIdx.y * TM;
    if (m0 >= cnt) return;
    int n0  = blockIdx.x * TN;
    int off = g_off[e];
    int tid = threadIdx.x, wid = tid >> 5, lane = tid & 31;
    int mw = wid & 3, nw = wid >> 2;
    uint32_t sbase = smem_u32(smem);

    int lrow = tid >> 1;
    bool rok = (m0 + lrow) < cnt;
    const char* ahi = (const char*)g_x_hi;
    const char* alo = (const char*)g_x_lo;
    if (rok) {
        size_t ao = (size_t)g_tok[e * CAP + m0 + lrow] * DD * 2;
        ahi = (const char*)g_x_hi + ao;
        alo = (const char*)g_x_lo + ao;
    }
    const char* bhi = (const char*)(g_w1_hi + ((size_t)e * HH + n0 + lrow) * DD);
    const char* blo = (const char*)(g_w1_lo + ((size_t)e * HH + n0 + lrow) * DD);

    float c[2][8][4];
#pragma unroll
    for (int i = 0; i < 2; i++)
#pragma unroll
        for (int j = 0; j < 8; j++)
#pragma unroll
            for (int q = 0; q < 4; q++) c[i][j][q] = 0.f;

    const int NC = DD / KC;  // 32
    load_chunk(sbase, ahi, alo, bhi, blo, rok, tid, 0);
    CP_COMMIT();
    for (int ch = 0; ch < NC; ch++) {
        if (ch + 1 < NC) {
            load_chunk(sbase + ((ch + 1) & 1) * STAGEB, ahi, alo, bhi, blo,
                       rok, tid, (ch + 1) * (KC * 2));
            CP_COMMIT();
            CP_WAIT1();
        } else {
            CP_WAIT0();
        }
        __syncthreads();
        uint32_t st = sbase + (ch & 1) * STAGEB;
        compute_chunk(st, st + MATB, st + 2 * MATB, st + 3 * MATB, mw, nw, lane, c);
        __syncthreads();
    }

    // epilogue: relu(+bias), split, store bf16 hi/lo
    const float* b1e = b1 + (size_t)e * HH + n0;
#pragma unroll
    for (int mf = 0; mf < 2; mf++) {
#pragma unroll
        for (int rr = 0; rr < 2; rr++) {
            int row = mw * 32 + mf * 16 + (lane >> 2) + rr * 8;
            int m = m0 + row;
            if (m >= cnt) continue;
            __nv_bfloat16* phi = g_h_hi + (size_t)(off + m) * HH + n0;
            __nv_bfloat16* plo = g_h_lo + (size_t)(off + m) * HH + n0;
#pragma unroll
            for (int j = 0; j < 8; j++) {
                int col = nw * 64 + j * 8 + 2 * (lane & 3);
                float v0 = fmaxf(c[mf][j][rr * 2 + 0] + b1e[col],     0.f);
                float v1 = fmaxf(c[mf][j][rr * 2 + 1] + b1e[col + 1], 0.f);
                __nv_bfloat162 h2, l2;
                h2.x = __float2bfloat16(v0);
                h2.y = __float2bfloat16(v1);
                l2.x = __float2bfloat16(v0 - __bfloat162float(h2.x));
                l2.y = __float2bfloat16(v1 - __bfloat162float(h2.y));
                *(__nv_bfloat162*)(phi + col) = h2;
                *(__nv_bfloat162*)(plo + col) = l2;
            }
        }
    }
}

// GEMM2: out[tok] += gate * (h @ W2^T + b2)
__global__ void __launch_bounds__(256) k_mm2(const float* __restrict__ b2,
                                             float* __restrict__ out) {
    extern __shared__ char smem[];
    int e   = blockIdx.z;
    int cnt = g_cnt[e];
    int m0  = blockIdx.y * TM;
    if (m0 >= cnt) return;
    int n0  = blockIdx.x * TN;
    int off = g_off[e];
    int tid = threadIdx.x, wid = tid >> 5, lane = tid & 31;
    int mw = wid & 3, nw = wid >> 2;
    uint32_t sbase = smem_u32(smem);

    int lrow = tid >> 1;
    bool rok = (m0 + lrow) < cnt;
    const char* ahi = (const char*)(g_h_hi + (size_t)(off + m0 + lrow) * HH);
    const char* alo = (const char*)(g_h_lo + (size_t)(off + m0 + lrow) * HH);
    const char* bhi = (const char*)(g_w2_hi + ((size_t)e * DD + n0 + lrow) * HH);
    const char* blo = (const char*)(g_w2_lo + ((size_t)e * DD + n0 + lrow) * HH);

    float c[2][8][4];
#pragma unroll
    for (int i = 0; i < 2; i++)
#pragma unroll
        for (int j = 0; j < 8; j++)
#pragma unroll
            for (int q = 0; q < 4; q++) c[i][j][q] = 0.f;

    const int NC = HH / KC;  // 64
    load_chunk(sbase, ahi, alo, bhi, blo, rok, tid, 0);
    CP_COMMIT();
    for (int ch = 0; ch < NC; ch++) {
        if (ch + 1 < NC) {
            load_chunk(sbase + ((ch + 1) & 1) * STAGEB, ahi, alo, bhi, blo,
                       rok, tid, (ch + 1) * (KC * 2));
            CP_COMMIT();
            CP_WAIT1();
        } else {
            CP_WAIT0();
        }
        __syncthreads();
        uint32_t st = sbase + (ch & 1) * STAGEB;
        compute_chunk(st, st + MATB, st + 2 * MATB, st + 3 * MATB, mw, nw, lane, c);
        __syncthreads();
    }

    const float* b2e = b2 + (size_t)e * DD + n0;
#pragma unroll
    for (int mf = 0; mf < 2; mf++) {
#pragma unroll
        for (int rr = 0; rr < 2; rr++) {
            int row = mw * 32 + mf * 16 + (lane >> 2) + rr * 8;
            int m = m0 + row;
            if (m >= cnt) continue;
            int   tok  = g_tok[e * CAP + m];
            float gate = g_gate[e * CAP + m];
            float* orow = out + (size_t)tok * DD + n0;
#pragma unroll
            for (int j = 0; j < 8; j++) {
                int col = nw * 64 + j * 8 + 2 * (lane & 3);
                atomicAdd(orow + col,     gate * (c[mf][j][rr * 2 + 0] + b2e[col]));
                atomicAdd(orow + col + 1, gate * (c[mf][j][rr * 2 + 1] + b2e[col + 1]));
            }
        }
    }
}

// ---------------- launch ------------------------------------------------------
extern "C" void kernel_launch(void* const* d_in, const int* in_sizes, int n_in,
                              void* d_out, int out_size) {
    const float* x  = (const float*)d_in[0];
    const float* Wr = (const float*)d_in[1];
    const float* br = (const float*)d_in[2];
    const float* W1 = (const float*)d_in[3];
    const float* b1 = (const float*)d_in[4];
    const float* W2 = (const float*)d_in[5];
    const float* b2 = (const float*)d_in[6];
    float* out = (float*)d_out;

    cudaFuncSetAttribute(k_mm1, cudaFuncAttributeMaxDynamicSharedMemorySize, SMEM_BYTES);
    cudaFuncSetAttribute(k_mm2, cudaFuncAttributeMaxDynamicSharedMemorySize, SMEM_BYTES);

    int n4 = out_size / 4;
    k_zero_out<<<(n4 + 255) / 256, 256>>>(out, n4);
    k_init<<<1, 32>>>();
    k_conv_x<<<(N_TOK * DD / 4 + 255) / 256, 256>>>(x);
    k_conv_w<<<dim3(HH / 32, DD / 32, EE), dim3(32, 8)>>>(W1, 1, DD, HH);
    k_conv_w<<<dim3(DD / 32, HH / 32, EE), dim3(32, 8)>>>(W2, 2, HH, DD);
    k_router<<<(N_TOK * 32 + 255) / 256, 256>>>(x, Wr, br);
    k_offsets<<<1, 1>>>();
    k_mm1<<<dim3(HH / TN, N_TOK / TM, EE), 256, SMEM_BYTES>>>(b1);
    k_mm2<<<dim3(DD / TN, N_TOK / TM, EE), 256, SMEM_BYTES>>>(b2, out);
}

// round 5
// speedup vs baseline: 2.0916x; 1.0105x over previous
#include <cuda_runtime.h>
#include <cuda_bf16.h>
#include <cstdint>
#include <math.h>

#define N_TOK 4096
#define DD 1024
#define EE 8
#define HH 2048
#define CAP 4096

#define TM 128
#define TN 128
#define KC 32            // bf16 k-elements per smem chunk
#define ASTRIDE 80       // smem row stride bytes (64B data + 16B pad)
#define MATB (128 * ASTRIDE)          // 10240 B per matrix
#define STAGEB (4 * MATB)             // Ahi Alo Bhi Blo
#define SMEM_BYTES (2 * STAGEB)       // 81920 (2 CTAs/SM fit in 228KB)

// ---------------- scratch (static __device__; no runtime allocation) --------
__device__ int   g_cnt[EE];
__device__ int   g_off[EE];
__device__ int   g_tok[EE * CAP];
__device__ float g_gate[EE * CAP];
__device__ __align__(256) __nv_bfloat16 g_x_hi[(size_t)N_TOK * DD];
__device__ __align__(256) __nv_bfloat16 g_x_lo[(size_t)N_TOK * DD];
__device__ __align__(256) __nv_bfloat16 g_w1_hi[(size_t)EE * HH * DD];  // [e][n=H][k=D]
__device__ __align__(256) __nv_bfloat16 g_w1_lo[(size_t)EE * HH * DD];
__device__ __align__(256) __nv_bfloat16 g_w2_hi[(size_t)EE * DD * HH];  // [e][n=D][k=H]
__device__ __align__(256) __nv_bfloat16 g_w2_lo[(size_t)EE * DD * HH];
__device__ __align__(256) __nv_bfloat16 g_h_hi[(size_t)(2 * N_TOK + TM) * HH];
__device__ __align__(256) __nv_bfloat16 g_h_lo[(size_t)(2 * N_TOK + TM) * HH];

// ---------------- PTX helpers -----------------------------------------------
__device__ __forceinline__ uint32_t smem_u32(const void* p) {
    uint32_t a;
    asm("{ .reg .u64 t; cvta.to.shared.u64 t, %1; cvt.u32.u64 %0, t; }"
        : "=r"(a) : "l"(p));
    return a;
}

__device__ __forceinline__ void cp16(uint32_t dst, const void* src, int sz) {
    asm volatile("cp.async.cg.shared.global [%0], [%1], 16, %2;"
                 :: "r"(dst), "l"(src), "r"(sz));
}
#define CP_COMMIT() asm volatile("cp.async.commit_group;" ::: "memory")
#define CP_WAIT1()  asm volatile("cp.async.wait_group 1;" ::: "memory")
#define CP_WAIT0()  asm volatile("cp.async.wait_group 0;" ::: "memory")

#define LDSM4(R, a) \
    asm volatile("ldmatrix.sync.aligned.m8n8.x4.shared.b16 {%0,%1,%2,%3}, [%4];" \
                 : "=r"((R)[0]), "=r"((R)[1]), "=r"((R)[2]), "=r"((R)[3]) : "r"(a))

#define MMA(C, A, B0, B1) \
    asm volatile("mma.sync.aligned.m16n8k16.row.col.f32.bf16.bf16.f32 " \
                 "{%0,%1,%2,%3}, {%4,%5,%6,%7}, {%8,%9}, {%0,%1,%2,%3};" \
                 : "+f"((C)[0]), "+f"((C)[1]), "+f"((C)[2]), "+f"((C)[3]) \
                 : "r"((A)[0]), "r"((A)[1]), "r"((A)[2]), "r"((A)[3]), \
                   "r"(B0), "r"(B1))

// ---------------- fused pre: zero out + reset counters -----------------------
__global__ void k_pre(float* __restrict__ out, int n4) {
    int i = blockIdx.x * blockDim.x + threadIdx.x;
    if (i < n4) ((float4*)out)[i] = make_float4(0.f, 0.f, 0.f, 0.f);
    if (blockIdx.x == 0 && threadIdx.x < EE) g_cnt[threadIdx.x] = 0;
}

// Transpose + split both weights in one launch.
// z < EE: W1 (K=DD, N=HH); z >= EE: W2 (K=HH, N=DD)
__global__ void k_conv_w(const float* __restrict__ W1f,
                         const float* __restrict__ W2f) {
    __shared__ float t[32][33];
    bool isW1 = blockIdx.z < EE;
    int e = isW1 ? blockIdx.z : blockIdx.z - EE;
    int K = isW1 ? DD : HH;
    int N = isW1 ? HH : DD;
    int n0 = blockIdx.x * 32;
    int k0 = blockIdx.y * 32;
    if (n0 >= N || k0 >= K) return;
    const float* We = (isW1 ? W1f : W2f) + (size_t)e * K * N;
    for (int r = threadIdx.y; r < 32; r += 8)
        t[r][threadIdx.x] = We[(size_t)(k0 + r) * N + n0 + threadIdx.x];
    __syncthreads();
    __nv_bfloat16* dhi = isW1 ? g_w1_hi : g_w2_hi;
    __nv_bfloat16* dlo = isW1 ? g_w1_lo : g_w2_lo;
    size_t base = (size_t)e * K * N;
    // 256 threads -> (k-pair, n) mapping: 16 k-pairs x 16 n rows, 2 n-iterations
    int tid = threadIdx.y * 32 + threadIdx.x;
    int kp  = tid & 15;          // k pair index: k = 2*kp, 2*kp+1
    int nr0 = tid >> 4;          // 0..15
#pragma unroll
    for (int it = 0; it < 2; it++) {
        int r = nr0 + it * 16;   // n within tile
        float v0 = t[2 * kp][r];
        float v1 = t[2 * kp + 1][r];
        __nv_bfloat162 h2, l2;
        h2.x = __float2bfloat16(v0);
        h2.y = __float2bfloat16(v1);
        l2.x = __float2bfloat16(v0 - __bfloat162float(h2.x));
        l2.y = __float2bfloat16(v1 - __bfloat162float(h2.y));
        size_t o = base + (size_t)(n0 + r) * K + k0 + 2 * kp;
        *(__nv_bfloat162*)(dhi + o) = h2;
        *(__nv_bfloat162*)(dlo + o) = l2;
    }
}

// Router fused with x split conversion (warp reads the row anyway).
__global__ void k_router(const float* __restrict__ x,
                         const float* __restrict__ Wr,
                         const float* __restrict__ br) {
    int gwarp = (blockIdx.x * blockDim.x + threadIdx.x) >> 5;
    int lane  = threadIdx.x & 31;
    if (gwarp >= N_TOK) return;
    const float* xr = x + (size_t)gwarp * DD;
    __nv_bfloat16* xh = g_x_hi + (size_t)gwarp * DD;
    __nv_bfloat16* xl = g_x_lo + (size_t)gwarp * DD;
    float acc[EE];
#pragma unroll
    for (int e = 0; e < EE; e++) acc[e] = 0.f;
    for (int d = lane; d < DD; d += 32) {
        float xv = xr[d];
        __nv_bfloat16 hi = __float2bfloat16(xv);
        xh[d] = hi;
        xl[d] = __float2bfloat16(xv - __bfloat162float(hi));
        const float* w = Wr + d * EE;
#pragma unroll
        for (int e = 0; e < EE; e++) acc[e] += xv * w[e];
    }
#pragma unroll
    for (int e = 0; e < EE; e++) {
#pragma unroll
        for (int o = 16; o > 0; o >>= 1)
            acc[e] += __shfl_down_sync(0xffffffffu, acc[e], o);
    }
    if (lane == 0) {
        float lg[EE];
#pragma unroll
        for (int e = 0; e < EE; e++) lg[e] = acc[e] + br[e];
        int i1 = 0;
#pragma unroll
        for (int e = 1; e < EE; e++) if (lg[e] > lg[i1]) i1 = e;
        int i2 = (i1 == 0) ? 1 : 0;
#pragma unroll
        for (int e = 0; e < EE; e++)
            if (e != i1 && lg[e] > lg[i2]) i2 = e;
        float e2 = expf(lg[i2] - lg[i1]);
        float s  = 1.0f + e2;
        int s1 = atomicAdd(&g_cnt[i1], 1);
        g_tok[i1 * CAP + s1]  = gwarp;
        g_gate[i1 * CAP + s1] = 1.0f / s;
        int s2 = atomicAdd(&g_cnt[i2], 1);
        g_tok[i2 * CAP + s2]  = gwarp;
        g_gate[i2 * CAP + s2] = e2 / s;
    }
}

__global__ void k_offsets() {
    int o = 0;
    for (int e = 0; e < EE; e++) { g_off[e] = o; o += g_cnt[e]; }
}

// ---------------- HMMA compute core ------------------------------------------
// Warp tile 32(m) x 64(n). 3-product split-bf16, fp32 accumulate.
// B fragments loaded per-ng to keep register liveness low (target 2 CTAs/SM).
__device__ __forceinline__ void compute_chunk(
    uint32_t sA_hi, uint32_t sA_lo, uint32_t sB_hi, uint32_t sB_lo,
    int mw, int nw, int lane, float c[2][8][4]) {
#pragma unroll
    for (int ks = 0; ks < 2; ks++) {
        int kb = ks * 32 + (lane >> 4) * 16;   // byte offset within row
        uint32_t ahi[2][4], alo[2][4];
#pragma unroll
        for (int mf = 0; mf < 2; mf++) {
            uint32_t off = (uint32_t)(mw * 32 + mf * 16 + (lane & 15)) * ASTRIDE + kb;
            LDSM4(ahi[mf], sA_hi + off);
            LDSM4(alo[mf], sA_lo + off);
        }
#pragma unroll
        for (int ng = 0; ng < 4; ng++) {
            uint32_t bh[4], bl[4];
            uint32_t off = (uint32_t)(nw * 64 + ng * 16 + (lane & 15)) * ASTRIDE + kb;
            LDSM4(bh, sB_hi + off);
            LDSM4(bl, sB_lo + off);
#pragma unroll
            for (int mf = 0; mf < 2; mf++) {
                MMA(c[mf][2 * ng],     ahi[mf], bh[0], bh[2]);
                MMA(c[mf][2 * ng + 1], ahi[mf], bh[1], bh[3]);
                MMA(c[mf][2 * ng],     ahi[mf], bl[0], bl[2]);
                MMA(c[mf][2 * ng + 1], ahi[mf], bl[1], bl[3]);
                MMA(c[mf][2 * ng],     alo[mf], bh[0], bh[2]);
                MMA(c[mf][2 * ng + 1], alo[mf], bh[1], bh[3]);
            }
        }
    }
}

// issue one chunk's cp.async loads (per thread: 8 x 16B)
__device__ __forceinline__ void load_chunk(
    uint32_t stage, const char* ahi, const char* alo,
    const char* bhi, const char* blo, bool rok, int tid, int kbyte) {
    int row = tid >> 1;
    int j0  = (tid & 1) * 2;
    int asz = rok ? 16 : 0;
#pragma unroll
    for (int j = j0; j < j0 + 2; j++) {
        uint32_t so = (uint32_t)row * ASTRIDE + j * 16;
        int go = kbyte + j * 16;
        cp16(stage + 0 * MATB + so, ahi + go, asz);
        cp16(stage + 1 * MATB + so, alo + go, asz);
        cp16(stage + 2 * MATB + so, bhi + go, 16);
        cp16(stage + 3 * MATB + so, blo + go, 16);
    }
}

// GEMM1: h = relu(Xg @ W1^T + b1) -> split g_h_hi/lo
__global__ void __launch_bounds__(256, 2) k_mm1(const float* __restrict__ b1) {
    extern __shared__ char smem[];
    int e   = blockIdx.z;
    int cnt = g_cnt[e];
    int m0  = blockIdx.y * TM;
    if (m0 >= cnt) return;
    int n0  = blockIdx.x * TN;
    int off = g_off[e];
    int tid = threadIdx.x, wid = tid >> 5, lane = tid & 31;
    int mw = wid & 3, nw = wid >> 2;
    uint32_t sbase = smem_u32(smem);

    int lrow = tid >> 1;
    bool rok = (m0 + lrow) < cnt;
    const char* ahi = (const char*)g_x_hi;
    const char* alo = (const char*)g_x_lo;
    if (rok) {
        size_t ao = (size_t)g_tok[e * CAP + m0 + lrow] * DD * 2;
        ahi = (const char*)g_x_hi + ao;
        alo = (const char*)g_x_lo + ao;
    }
    const char* bhi = (const char*)(g_w1_hi + ((size_t)e * HH + n0 + lrow) * DD);
    const char* blo = (const char*)(g_w1_lo + ((size_t)e * HH + n0 + lrow) * DD);

    float c[2][8][4];
#pragma unroll
    for (int i = 0; i < 2; i++)
#pragma unroll
        for (int j = 0; j < 8; j++)
#pragma unroll
            for (int q = 0; q < 4; q++) c[i][j][q] = 0.f;

    const int NC = DD / KC;  // 32
    load_chunk(sbase, ahi, alo, bhi, blo, rok, tid, 0);
    CP_COMMIT();
    for (int ch = 0; ch < NC; ch++) {
        if (ch + 1 < NC) {
            load_chunk(sbase + ((ch + 1) & 1) * STAGEB, ahi, alo, bhi, blo,
                       rok, tid, (ch + 1) * (KC * 2));
            CP_COMMIT();
            CP_WAIT1();
        } else {
            CP_WAIT0();
        }
        __syncthreads();
        uint32_t st = sbase + (ch & 1) * STAGEB;
        compute_chunk(st, st + MATB, st + 2 * MATB, st + 3 * MATB, mw, nw, lane, c);
        __syncthreads();
    }

    // epilogue: relu(+bias), split, store bf16 hi/lo
    const float* b1e = b1 + (size_t)e * HH + n0;
#pragma unroll
    for (int mf = 0; mf < 2; mf++) {
#pragma unroll
        for (int rr = 0; rr < 2; rr++) {
            int row = mw * 32 + mf * 16 + (lane >> 2) + rr * 8;
            int m = m0 + row;
            if (m >= cnt) continue;
            __nv_bfloat16* phi = g_h_hi + (size_t)(off + m) * HH + n0;
            __nv_bfloat16* plo = g_h_lo + (size_t)(off + m) * HH + n0;
#pragma unroll
            for (int j = 0; j < 8; j++) {
                int col = nw * 64 + j * 8 + 2 * (lane & 3);
                float v0 = fmaxf(c[mf][j][rr * 2 + 0] + b1e[col],     0.f);
                float v1 = fmaxf(c[mf][j][rr * 2 + 1] + b1e[col + 1], 0.f);
                __nv_bfloat162 h2, l2;
                h2.x = __float2bfloat16(v0);
                h2.y = __float2bfloat16(v1);
                l2.x = __float2bfloat16(v0 - __bfloat162float(h2.x));
                l2.y = __float2bfloat16(v1 - __bfloat162float(h2.y));
                *(__nv_bfloat162*)(phi + col) = h2;
                *(__nv_bfloat162*)(plo + col) = l2;
            }
        }
    }
}

// GEMM2: out[tok] += gate * (h @ W2^T + b2)
__global__ void __launch_bounds__(256, 2) k_mm2(const float* __restrict__ b2,
                                                float* __restrict__ out) {
    extern __shared__ char smem[];
    int e   = blockIdx.z;
    int cnt = g_cnt[e];
    int m0  = blockIdx.y * TM;
    if (m0 >= cnt) return;
    int n0  = blockIdx.x * TN;
    int off = g_off[e];
    int tid = threadIdx.x, wid = tid >> 5, lane = tid & 31;
    int mw = wid & 3, nw = wid >> 2;
    uint32_t sbase = smem_u32(smem);

    int lrow = tid >> 1;
    bool rok = (m0 + lrow) < cnt;
    const char* ahi = (const char*)(g_h_hi + (size_t)(off + m0 + lrow) * HH);
    const char* alo = (const char*)(g_h_lo + (size_t)(off + m0 + lrow) * HH);
    const char* bhi = (const char*)(g_w2_hi + ((size_t)e * DD + n0 + lrow) * HH);
    const char* blo = (const char*)(g_w2_lo + ((size_t)e * DD + n0 + lrow) * HH);

    float c[2][8][4];
#pragma unroll
    for (int i = 0; i < 2; i++)
#pragma unroll
        for (int j = 0; j < 8; j++)
#pragma unroll
            for (int q = 0; q < 4; q++) c[i][j][q] = 0.f;

    const int NC = HH / KC;  // 64
    load_chunk(sbase, ahi, alo, bhi, blo, rok, tid, 0);
    CP_COMMIT();
    for (int ch = 0; ch < NC; ch++) {
        if (ch + 1 < NC) {
            load_chunk(sbase + ((ch + 1) & 1) * STAGEB, ahi, alo, bhi, blo,
                       rok, tid, (ch + 1) * (KC * 2));
            CP_COMMIT();
            CP_WAIT1();
        } else {
            CP_WAIT0();
        }
        __syncthreads();
        uint32_t st = sbase + (ch & 1) * STAGEB;
        compute_chunk(st, st + MATB, st + 2 * MATB, st + 3 * MATB, mw, nw, lane, c);
        __syncthreads();
    }

    const float* b2e = b2 + (size_t)e * DD + n0;
#pragma unroll
    for (int mf = 0; mf < 2; mf++) {
#pragma unroll
        for (int rr = 0; rr < 2; rr++) {
            int row = mw * 32 + mf * 16 + (lane >> 2) + rr * 8;
            int m = m0 + row;
            if (m >= cnt) continue;
            int   tok  = g_tok[e * CAP + m];
            float gate = g_gate[e * CAP + m];
            float* orow = out + (size_t)tok * DD + n0;
#pragma unroll
            for (int j = 0; j < 8; j++) {
                int col = nw * 64 + j * 8 + 2 * (lane & 3);
                atomicAdd(orow + col,     gate * (c[mf][j][rr * 2 + 0] + b2e[col]));
                atomicAdd(orow + col + 1, gate * (c[mf][j][rr * 2 + 1] + b2e[col + 1]));
            }
        }
    }
}

// ---------------- launch ------------------------------------------------------
extern "C" void kernel_launch(void* const* d_in, const int* in_sizes, int n_in,
                              void* d_out, int out_size) {
    const float* x  = (const float*)d_in[0];
    const float* Wr = (const float*)d_in[1];
    const float* br = (const float*)d_in[2];
    const float* W1 = (const float*)d_in[3];
    const float* b1 = (const float*)d_in[4];
    const float* W2 = (const float*)d_in[5];
    const float* b2 = (const float*)d_in[6];
    float* out = (float*)d_out;

    cudaFuncSetAttribute(k_mm1, cudaFuncAttributeMaxDynamicSharedMemorySize, SMEM_BYTES);
    cudaFuncSetAttribute(k_mm2, cudaFuncAttributeMaxDynamicSharedMemorySize, SMEM_BYTES);

    int n4 = out_size / 4;
    // launch order keeps mm1/mm2 at positions 5/6 so the ncu -s5 -c1 window
    // lands on a GEMM kernel regardless of skip-index convention.
    k_pre<<<(n4 + 255) / 256, 256>>>(out, n4);                       // 1
    k_conv_w<<<dim3(HH / 32, HH / 32, 2 * EE), dim3(32, 8)>>>(W1, W2); // 2
    k_router<<<(N_TOK * 32 + 255) / 256, 256>>>(x, Wr, br);          // 3
    k_offsets<<<1, 1>>>();                                           // 4
    k_mm1<<<dim3(HH / TN, N_TOK / TM, EE), 256, SMEM_BYTES>>>(b1);   // 5
    k_mm2<<<dim3(DD / TN, N_TOK / TM, EE), 256, SMEM_BYTES>>>(b2, out); // 6
}